// round 5
// baseline (speedup 1.0000x reference)
#include <cuda_runtime.h>
#include <math_constants.h>

// GraphSAGE split into two kernels:
//  K1: masked-max aggregation + relu  -> g_neigh (device scratch, 1 MB)
//      2048 blocks x 64 threads (1 row/block, 2 warps scan half-adj-row each)
//      -> all blocks resident, near-perfect SM balance, deep warp pool to
//         hide gather latency (the fused kernel's 1-block SMs could not).
//  K2: out = [feat || neigh] @ W + b   (identical to R4's proven GEMM phase)
//      256 blocks x 512 threads, W read exactly once per block, FFMA2.

#define B_DIM 4
#define N_DIM 512
#define C_DIM 128
#define OUT_DIM 128
#define ROWS 8
#define TOTAL_ROWS (B_DIM * N_DIM)

__device__ float g_neigh[TOTAL_ROWS * C_DIM];   // relu'd neighbor max

// ===================== K1: aggregation =====================
__global__ __launch_bounds__(64)
void k1_aggregate(const float* __restrict__ adj,
                  const float* __restrict__ feat)
{
    __shared__ __align__(16) unsigned short idxbuf[2][264];
    __shared__ __align__(16) float aggbuf[2][C_DIM];

    const int tid  = threadIdx.x;
    const int half = tid >> 5;            // warp 0/1
    const int lane = tid & 31;

    const int row = blockIdx.x;           // global row over B*N
    const int b = row >> 9;               // /512
    const int i = row & (N_DIM - 1);

    const float* __restrict__ fb = feat + (size_t)b * N_DIM * C_DIM;
    const float* __restrict__ adjrow =
        adj + ((size_t)b * N_DIM + i) * N_DIM + half * (N_DIM / 2);

    unsigned short* __restrict__ myidx = idxbuf[half];
    const unsigned lt = (1u << lane) - 1u;

    // ---- compact neighbor indices (ballot + prefix popc) ----
    int total = 0;
    #pragma unroll
    for (int c = 0; c < N_DIM / 2; c += 128) {
        float4 a = reinterpret_cast<const float4*>(adjrow + c)[lane];
        const int cbase = half * (N_DIM / 2) + c + 4 * lane;
        {
            unsigned m = __ballot_sync(0xffffffffu, a.x > 0.0f);
            if (a.x > 0.0f) myidx[total + __popc(m & lt)] = (unsigned short)(cbase + 0);
            total += __popc(m);
        }
        {
            unsigned m = __ballot_sync(0xffffffffu, a.y > 0.0f);
            if (a.y > 0.0f) myidx[total + __popc(m & lt)] = (unsigned short)(cbase + 1);
            total += __popc(m);
        }
        {
            unsigned m = __ballot_sync(0xffffffffu, a.z > 0.0f);
            if (a.z > 0.0f) myidx[total + __popc(m & lt)] = (unsigned short)(cbase + 2);
            total += __popc(m);
        }
        {
            unsigned m = __ballot_sync(0xffffffffu, a.w > 0.0f);
            if (a.w > 0.0f) myidx[total + __popc(m & lt)] = (unsigned short)(cbase + 3);
            total += __popc(m);
        }
    }
    __syncwarp();

    // ---- gather + running max, MLP=8 ----
    float4 acc0 = make_float4(-CUDART_INF_F, -CUDART_INF_F, -CUDART_INF_F, -CUDART_INF_F);
    float4 acc1 = acc0, acc2 = acc0, acc3 = acc0;

    if (total > 0) {
        const int padded = (total + 7) & ~7;
        unsigned short lastv = myidx[total - 1];
        __syncwarp();
        if (lane < padded - total) myidx[total + lane] = lastv;
        __syncwarp();

        const uint4* __restrict__ ivec = reinterpret_cast<const uint4*>(myidx);
        for (int k = 0; k < padded; k += 8) {
            uint4 I = ivec[k >> 3];
            int j0 =  I.x        & 0xffff;
            int j1 = (I.x >> 16) & 0xffff;
            int j2 =  I.y        & 0xffff;
            int j3 = (I.y >> 16) & 0xffff;
            int j4 =  I.z        & 0xffff;
            int j5 = (I.z >> 16) & 0xffff;
            int j6 =  I.w        & 0xffff;
            int j7 = (I.w >> 16) & 0xffff;

            float4 f0 = reinterpret_cast<const float4*>(fb + (size_t)j0 * C_DIM)[lane];
            float4 f1 = reinterpret_cast<const float4*>(fb + (size_t)j1 * C_DIM)[lane];
            float4 f2 = reinterpret_cast<const float4*>(fb + (size_t)j2 * C_DIM)[lane];
            float4 f3 = reinterpret_cast<const float4*>(fb + (size_t)j3 * C_DIM)[lane];
            float4 f4 = reinterpret_cast<const float4*>(fb + (size_t)j4 * C_DIM)[lane];
            float4 f5 = reinterpret_cast<const float4*>(fb + (size_t)j5 * C_DIM)[lane];
            float4 f6 = reinterpret_cast<const float4*>(fb + (size_t)j6 * C_DIM)[lane];
            float4 f7 = reinterpret_cast<const float4*>(fb + (size_t)j7 * C_DIM)[lane];

            acc0.x = fmaxf(acc0.x, f0.x); acc0.y = fmaxf(acc0.y, f0.y);
            acc0.z = fmaxf(acc0.z, f0.z); acc0.w = fmaxf(acc0.w, f0.w);
            acc1.x = fmaxf(acc1.x, f1.x); acc1.y = fmaxf(acc1.y, f1.y);
            acc1.z = fmaxf(acc1.z, f1.z); acc1.w = fmaxf(acc1.w, f1.w);
            acc2.x = fmaxf(acc2.x, f2.x); acc2.y = fmaxf(acc2.y, f2.y);
            acc2.z = fmaxf(acc2.z, f2.z); acc2.w = fmaxf(acc2.w, f2.w);
            acc3.x = fmaxf(acc3.x, f3.x); acc3.y = fmaxf(acc3.y, f3.y);
            acc3.z = fmaxf(acc3.z, f3.z); acc3.w = fmaxf(acc3.w, f3.w);

            acc0.x = fmaxf(acc0.x, f4.x); acc0.y = fmaxf(acc0.y, f4.y);
            acc0.z = fmaxf(acc0.z, f4.z); acc0.w = fmaxf(acc0.w, f4.w);
            acc1.x = fmaxf(acc1.x, f5.x); acc1.y = fmaxf(acc1.y, f5.y);
            acc1.z = fmaxf(acc1.z, f5.z); acc1.w = fmaxf(acc1.w, f5.w);
            acc2.x = fmaxf(acc2.x, f6.x); acc2.y = fmaxf(acc2.y, f6.y);
            acc2.z = fmaxf(acc2.z, f6.z); acc2.w = fmaxf(acc2.w, f6.w);
            acc3.x = fmaxf(acc3.x, f7.x); acc3.y = fmaxf(acc3.y, f7.y);
            acc3.z = fmaxf(acc3.z, f7.z); acc3.w = fmaxf(acc3.w, f7.w);
        }
    }

    float4 accA;
    accA.x = fmaxf(fmaxf(acc0.x, acc1.x), fmaxf(acc2.x, acc3.x));
    accA.y = fmaxf(fmaxf(acc0.y, acc1.y), fmaxf(acc2.y, acc3.y));
    accA.z = fmaxf(fmaxf(acc0.z, acc1.z), fmaxf(acc2.z, acc3.z));
    accA.w = fmaxf(fmaxf(acc0.w, acc1.w), fmaxf(acc2.w, acc3.w));
    reinterpret_cast<float4*>(&aggbuf[half][0])[lane] = accA;

    __syncthreads();

    // warp 0 combines halves + relu and writes to global scratch
    if (half == 0) {
        float4 a0 = reinterpret_cast<const float4*>(&aggbuf[0][0])[lane];
        float4 a1 = reinterpret_cast<const float4*>(&aggbuf[1][0])[lane];
        float4 nb;
        nb.x = fmaxf(0.0f, fmaxf(a0.x, a1.x));
        nb.y = fmaxf(0.0f, fmaxf(a0.y, a1.y));
        nb.z = fmaxf(0.0f, fmaxf(a0.z, a1.z));
        nb.w = fmaxf(0.0f, fmaxf(a0.w, a1.w));
        reinterpret_cast<float4*>(g_neigh + (size_t)row * C_DIM)[lane] = nb;
    }
}

// ===================== K2: fused linear layer =====================
__global__ __launch_bounds__(512)
void k2_gemm(const float* __restrict__ feat,
             const float* __restrict__ W,
             const float* __restrict__ bias,
             float* __restrict__ out)
{
    __shared__ __align__(16) float combT[2 * C_DIM][ROWS];   // 8 KB, k-major
    __shared__ __align__(16) float ps[3][ROWS][OUT_DIM];     // 12 KB partials

    const int tid = threadIdx.x;
    const int block_row0 = blockIdx.x * ROWS;

    // ---- stage combT: feat || neigh, k-major interleaved ----
    {
        const int r  = tid & 7;
        const int c8 = tid >> 3;           // 0..63
        const int gr = block_row0 + r;
        const int rb = gr >> 9;
        const int ri = gr & (N_DIM - 1);
        const float* __restrict__ frow =
            feat + ((size_t)rb * N_DIM + ri) * C_DIM;
        const float* __restrict__ nrow = g_neigh + (size_t)gr * C_DIM;
        #pragma unroll
        for (int j = 0; j < 2; ++j) {
            const int c = c8 + 64 * j;
            combT[c][r]         = frow[c];
            combT[C_DIM + c][r] = nrow[c];
        }
    }
    __syncthreads();

    // ---- GEMM: o = tid&127, ks = tid>>7 (4-way k-split, 64 k each) ----
    {
        const int o  = tid & (OUT_DIM - 1);
        const int ks = tid >> 7;

        const float* __restrict__ wp = W + (size_t)(ks * 64) * OUT_DIM + o;
        const float* __restrict__ cb = &combT[ks * 64][0];

        unsigned long long a01 = 0ull, a23 = 0ull, a45 = 0ull, a67 = 0ull;

        #pragma unroll 8
        for (int k = 0; k < 64; ++k) {
            float w = wp[(size_t)k * OUT_DIM];
            unsigned long long wpk;
            asm("mov.b64 %0, {%1, %1};" : "=l"(wpk) : "f"(w));

            const double2 q0 = *reinterpret_cast<const double2*>(cb + k * 8);
            const double2 q1 = *reinterpret_cast<const double2*>(cb + k * 8 + 4);
            unsigned long long p01 = __double_as_longlong(q0.x);
            unsigned long long p23 = __double_as_longlong(q0.y);
            unsigned long long p45 = __double_as_longlong(q1.x);
            unsigned long long p67 = __double_as_longlong(q1.y);

            asm("fma.rn.f32x2 %0, %1, %2, %0;" : "+l"(a01) : "l"(p01), "l"(wpk));
            asm("fma.rn.f32x2 %0, %1, %2, %0;" : "+l"(a23) : "l"(p23), "l"(wpk));
            asm("fma.rn.f32x2 %0, %1, %2, %0;" : "+l"(a45) : "l"(p45), "l"(wpk));
            asm("fma.rn.f32x2 %0, %1, %2, %0;" : "+l"(a67) : "l"(p67), "l"(wpk));
        }

        float r0, r1, r2, r3, r4, r5, r6, r7;
        asm("mov.b64 {%0, %1}, %2;" : "=f"(r0), "=f"(r1) : "l"(a01));
        asm("mov.b64 {%0, %1}, %2;" : "=f"(r2), "=f"(r3) : "l"(a23));
        asm("mov.b64 {%0, %1}, %2;" : "=f"(r4), "=f"(r5) : "l"(a45));
        asm("mov.b64 {%0, %1}, %2;" : "=f"(r6), "=f"(r7) : "l"(a67));

        if (ks != 0) {
            float* p = &ps[ks - 1][0][o];
            p[0 * OUT_DIM] = r0;  p[1 * OUT_DIM] = r1;
            p[2 * OUT_DIM] = r2;  p[3 * OUT_DIM] = r3;
            p[4 * OUT_DIM] = r4;  p[5 * OUT_DIM] = r5;
            p[6 * OUT_DIM] = r6;  p[7 * OUT_DIM] = r7;
        }
        __syncthreads();
        if (ks == 0) {
            const float bv = bias[o];
            const float* p0 = &ps[0][0][o];
            const float* p1 = &ps[1][0][o];
            const float* p2 = &ps[2][0][o];
            float* __restrict__ op = out + (size_t)block_row0 * OUT_DIM + o;
            op[0 * OUT_DIM] = r0 + p0[0 * OUT_DIM] + p1[0 * OUT_DIM] + p2[0 * OUT_DIM] + bv;
            op[1 * OUT_DIM] = r1 + p0[1 * OUT_DIM] + p1[1 * OUT_DIM] + p2[1 * OUT_DIM] + bv;
            op[2 * OUT_DIM] = r2 + p0[2 * OUT_DIM] + p1[2 * OUT_DIM] + p2[2 * OUT_DIM] + bv;
            op[3 * OUT_DIM] = r3 + p0[3 * OUT_DIM] + p1[3 * OUT_DIM] + p2[3 * OUT_DIM] + bv;
            op[4 * OUT_DIM] = r4 + p0[4 * OUT_DIM] + p1[4 * OUT_DIM] + p2[4 * OUT_DIM] + bv;
            op[5 * OUT_DIM] = r5 + p0[5 * OUT_DIM] + p1[5 * OUT_DIM] + p2[5 * OUT_DIM] + bv;
            op[6 * OUT_DIM] = r6 + p0[6 * OUT_DIM] + p1[6 * OUT_DIM] + p2[6 * OUT_DIM] + bv;
            op[7 * OUT_DIM] = r7 + p0[7 * OUT_DIM] + p1[7 * OUT_DIM] + p2[7 * OUT_DIM] + bv;
        }
    }
}

extern "C" void kernel_launch(void* const* d_in, const int* in_sizes, int n_in,
                              void* d_out, int out_size)
{
    (void)in_sizes; (void)n_in; (void)out_size;
    const float* adj  = (const float*)d_in[0];   // [B,N,N]
    const float* feat = (const float*)d_in[1];   // [B,N,C]
    const float* W    = (const float*)d_in[2];   // [2C,OUT]
    const float* bias = (const float*)d_in[3];   // [OUT]
    float* out        = (float*)d_out;           // [B,N,OUT]

    k1_aggregate<<<TOTAL_ROWS, 64>>>(adj, feat);
    k2_gemm<<<TOTAL_ROWS / ROWS, 512>>>(feat, W, bias, out);
}